// round 12
// baseline (speedup 1.0000x reference)
#include <cuda_runtime.h>
#include <cuda_fp16.h>
#include <cstdint>

#define NB  32
#define C1  64
#define C2  384
#define HH  56
#define HW  3136
#define EPSV 1e-5f
#define XS  36            // smem row stride in 32-bit words (conflict-free for ldmatrix)

// ---------------- scratch (device globals; no allocation allowed) ----------------
__device__ __half   g_hf  [(size_t)NB * C2 * HW];     // expand output fp16 planes (dw input)
__device__ uint32_t g_h2  [(size_t)NB * 192 * HW];    // dw output, packed fp16 ch-pair words
__device__ uint32_t g_weh [384 * 32];                  // w_expand fp16-pair words [c][j]
__device__ uint32_t g_wph [64 * 192];                  // w_proj   fp16-pair words [c][j]
__device__ float g_ctxsum[NB * C2];
__device__ float g_bias2 [NB * C2];
__device__ float g_s1[C2], g_sh1[C2];
__device__ float g_s2[C2], g_sh2[C2];
__device__ float g_s3[C1], g_sh3[C1];

// ---------------- helpers ----------------
__device__ __forceinline__ uint32_t hpack2(float f0, float f1) {
    __half2 H = __floats2half2_rn(f0, f1);
    return *reinterpret_cast<uint32_t*>(&H);
}

__device__ __forceinline__ void mma16816(float* c, const uint32_t* a, uint32_t b0, uint32_t b1) {
    asm volatile(
        "mma.sync.aligned.m16n8k16.row.col.f32.f16.f16.f32 "
        "{%0,%1,%2,%3},{%4,%5,%6,%7},{%8,%9},{%0,%1,%2,%3};"
        : "+f"(c[0]), "+f"(c[1]), "+f"(c[2]), "+f"(c[3])
        : "r"(a[0]), "r"(a[1]), "r"(a[2]), "r"(a[3]), "r"(b0), "r"(b1));
}

__device__ __forceinline__ void ldsm4(uint32_t* r, uint32_t addr) {
    asm volatile("ldmatrix.sync.aligned.m8n8.x4.shared.b16 {%0,%1,%2,%3},[%4];"
                 : "=r"(r[0]), "=r"(r[1]), "=r"(r[2]), "=r"(r[3]) : "r"(addr));
}

__device__ __forceinline__ void cpasync4(uint32_t dst, const void* src, bool valid) {
    asm volatile("cp.async.ca.shared.global [%0], [%1], 4, %2;"
                 :: "r"(dst), "l"(src), "r"(valid ? 4 : 0) : "memory");
}
__device__ __forceinline__ void cpasync_commit() {
    asm volatile("cp.async.commit_group;" ::: "memory");
}

__device__ __forceinline__ float clip6(float v) { return fminf(fmaxf(v, 0.f), 6.f); }

// ---------------- prep ----------------
__global__ void prep_kernel(const float* __restrict__ g1, const float* __restrict__ b1,
                            const float* __restrict__ m1, const float* __restrict__ v1,
                            const float* __restrict__ g2, const float* __restrict__ b2,
                            const float* __restrict__ m2, const float* __restrict__ v2,
                            const float* __restrict__ g3, const float* __restrict__ b3,
                            const float* __restrict__ m3, const float* __restrict__ v3,
                            const float* __restrict__ we, const float* __restrict__ wpj)
{
    int t = threadIdx.x;
    if (t < C2) {
        float s = g1[t] * rsqrtf(v1[t] + EPSV);
        g_s1[t] = s; g_sh1[t] = b1[t] - m1[t] * s;
        float s2 = g2[t] * rsqrtf(v2[t] + EPSV);
        g_s2[t] = s2; g_sh2[t] = b2[t] - m2[t] * s2;
    }
    if (t < C1) {
        float s = g3[t] * rsqrtf(v3[t] + EPSV);
        g_s3[t] = s; g_sh3[t] = b3[t] - m3[t] * s;
    }
    for (int i = t; i < NB * C2; i += blockDim.x) g_ctxsum[i] = 0.f;
    for (int i = t; i < 384 * 32; i += blockDim.x) {
        float2 wv = *(const float2*)(we + (size_t)i * 2);
        g_weh[i] = hpack2(wv.x, wv.y);
    }
    for (int i = t; i < 64 * 192; i += blockDim.x) {
        float2 wv = *(const float2*)(wpj + (size_t)i * 2);
        g_wph[i] = hpack2(wv.x, wv.y);
    }
}

// ======================= EXPAND: resident W + staged coalesced epilogue =====================
#define ESTG 68   // stage row stride (uint32 words), 16B-aligned rows, conflict-free
__global__ void __launch_bounds__(256, 2) expand_kernel(const float* __restrict__ x)
{
    extern __shared__ uint32_t sm[];
    uint32_t* xsh   = sm;                     // [128 px][XS]
    uint32_t* wsh   = xsh + 128 * XS;         // [384 ch][XS] full W
    uint32_t* stage = wsh + 384 * XS;         // [64 ch][ESTG] packed half2 output stage

    const int n    = blockIdx.y;
    const int pix0 = blockIdx.x * 128;
    const int tid  = threadIdx.x;
    const int wid  = tid >> 5;
    const int lane = tid & 31;
    const int g    = lane >> 2;
    const int tq   = lane & 3;
    const int wm   = wid & 1;
    const int wn   = wid >> 1;

    const uint32_t xshb = (uint32_t)__cvta_generic_to_shared(xsh);
    const uint32_t wshb = (uint32_t)__cvta_generic_to_shared(wsh);
    const int lrow = (lane & 7) + ((lane >> 3) & 1) * 8;
    const int loff = (lrow * XS + ((lane >> 4) * 4)) * 4;

    const float* xn = x + (size_t)n * C1 * HW;

    // X tile
    for (int idx = tid; idx < 128 * 32; idx += 256) {
        int j = idx >> 7, p = idx & 127;
        int pg = pix0 + p;
        float f0 = 0.f, f1 = 0.f;
        if (pg < HW) {
            f0 = xn[(size_t)(2 * j) * HW + pg];
            f1 = xn[(size_t)(2 * j + 1) * HW + pg];
        }
        xsh[p * XS + j] = hpack2(f0, f1);
    }
    // full W
    {
        const uint4* src = (const uint4*)g_weh;
        for (int i = tid; i < 3072; i += 256) {
            int c = i >> 3, jq = (i & 7) * 4;
            *(uint4*)&wsh[c * XS + jq] = src[i];
        }
    }
    __syncthreads();

    for (int ct = 0; ct < 6; ++ct) {
        const int cbase = ct * 64;

        float acc[2][4][4];
        #pragma unroll
        for (int mt = 0; mt < 2; ++mt)
            #pragma unroll
            for (int nt = 0; nt < 4; ++nt)
                #pragma unroll
                for (int i = 0; i < 4; ++i) acc[mt][nt][i] = 0.f;

        #pragma unroll
        for (int s = 0; s < 4; ++s) {
            const int soff = s * 32;
            uint32_t ah[2][4], bh[2][4];
            #pragma unroll
            for (int mt = 0; mt < 2; ++mt) {
                uint32_t off = (uint32_t)((cbase + wm * 32 + mt * 16) * XS * 4 + soff) + loff;
                ldsm4(ah[mt], wshb + off);
            }
            #pragma unroll
            for (int q = 0; q < 2; ++q) {
                uint32_t off = (uint32_t)((wn * 32 + q * 16) * XS * 4 + soff) + loff;
                ldsm4(bh[q], xshb + off);
            }
            #pragma unroll
            for (int mt = 0; mt < 2; ++mt)
                #pragma unroll
                for (int q = 0; q < 2; ++q) {
                    mma16816(acc[mt][2*q],   ah[mt], bh[q][0], bh[q][2]);
                    mma16816(acc[mt][2*q+1], ah[mt], bh[q][1], bh[q][3]);
                }
        }

        // ---- epilogue: BN1 + ReLU6, pool from regs, stage packed half2 ----
        #pragma unroll
        for (int mt = 0; mt < 2; ++mt) {
            int cl0 = wm * 32 + mt * 16 + g;       // local channel in chunk
            int cl8 = cl0 + 8;
            int c0 = cbase + cl0, c8 = cbase + cl8;
            float s0 = g_s1[c0], h0 = g_sh1[c0];
            float s8 = g_s1[c8], h8 = g_sh1[c8];
            float rs0 = 0.f, rs8 = 0.f;
            #pragma unroll
            for (int nt = 0; nt < 4; ++nt) {
                int p = pix0 + wn * 32 + nt * 8 + 2 * tq;
                float v00 = clip6(s0 * acc[mt][nt][0] + h0);
                float v01 = clip6(s0 * acc[mt][nt][1] + h0);
                float v10 = clip6(s8 * acc[mt][nt][2] + h8);
                float v11 = clip6(s8 * acc[mt][nt][3] + h8);
                int wcol = wn * 16 + nt * 4 + tq;
                stage[cl0 * ESTG + wcol] = hpack2(v00, v01);
                stage[cl8 * ESTG + wcol] = hpack2(v10, v11);
                if (p < HW) { rs0 += v00 + v01; rs8 += v10 + v11; }
            }
            rs0 += __shfl_xor_sync(0xffffffffu, rs0, 1);
            rs0 += __shfl_xor_sync(0xffffffffu, rs0, 2);
            rs8 += __shfl_xor_sync(0xffffffffu, rs8, 1);
            rs8 += __shfl_xor_sync(0xffffffffu, rs8, 2);
            if (tq == 0) {
                atomicAdd(&g_ctxsum[n * C2 + c0], rs0);
                atomicAdd(&g_ctxsum[n * C2 + c8], rs8);
            }
        }
        __syncthreads();
        // ---- coalesced copy-out: 16B per thread-iteration ----
        for (int i = tid; i < 1024; i += 256) {
            int c = i >> 4, k = i & 15;
            int pg = pix0 + 8 * k;
            if (pg < HW) {
                uint4 v = *(uint4*)&stage[c * ESTG + 4 * k];
                *(uint4*)(g_hf + ((size_t)(n * C2 + cbase + c)) * HW + pg) = v;
            }
        }
        __syncthreads();
    }
}

// ---------------- context bias ----------------
__global__ void ctxbias_kernel(const float* __restrict__ wctx)
{
    __shared__ float cs[C2];
    const int n = blockIdx.x;
    const int o = threadIdx.x;
    cs[o] = g_ctxsum[n * C2 + o] * (1.f / (float)HW);
    __syncthreads();
    const float* wr = wctx + o * C2;
    float a = 0.f;
    #pragma unroll 4
    for (int c = 0; c < C2; ++c) a += cs[c] * wr[c];
    g_bias2[n * C2 + o] = g_s2[o] * a + g_sh2[o];
}

// ---------------- depthwise 3x3: packed-half2 smem + sliding window ----------------
__global__ void __launch_bounds__(224) dw_kernel(const float* __restrict__ wdw)
{
    __shared__ uint32_t sp[HW];
    __shared__ float wd[18];
    __shared__ float bs[2], sc[2];

    const int jw = blockIdx.x;
    const int n  = blockIdx.y;
    const int t  = threadIdx.x;
    const int c0 = 2 * jw;

    const uint4* src0 = (const uint4*)(g_hf + ((size_t)(n * C2 + c0)) * HW);
    const uint4* src1 = (const uint4*)(g_hf + ((size_t)(n * C2 + c0 + 1)) * HW);
    #pragma unroll
    for (int i = t; i < HW / 8; i += 224) {
        uint4 a = src0[i];
        uint4 b = src1[i];
        const uint32_t* aw = (const uint32_t*)&a;
        const uint32_t* bw = (const uint32_t*)&b;
        #pragma unroll
        for (int k = 0; k < 4; ++k) {
            sp[8 * i + 2 * k]     = __byte_perm(aw[k], bw[k], 0x5410);
            sp[8 * i + 2 * k + 1] = __byte_perm(aw[k], bw[k], 0x7632);
        }
    }
    if (t < 18) wd[t] = wdw[c0 * 9 + t];
    if (t < 2)  { bs[t] = g_bias2[n * C2 + c0 + t]; sc[t] = g_s2[c0 + t]; }
    __syncthreads();

    const int col  = t % HH;
    const int q    = t / HH;
    const int rbeg = q * 14;
    const bool cl = (col > 0), cr = (col < HH - 1);
    uint32_t* op = g_h2 + ((size_t)(n * 192 + jw)) * HW;
    const float b0 = bs[0], b1 = bs[1], s0 = sc[0], s1 = sc[1];

    float2 pl, pm, pr, cl2, cm, cr2;
    const float2 z2 = make_float2(0.f, 0.f);

    if (rbeg > 0) {
        const uint32_t* rp = sp + (rbeg - 1) * HH + col;
        pl = cl ? __half22float2(*(const __half2*)&rp[-1]) : z2;
        pm = __half22float2(*(const __half2*)&rp[0]);
        pr = cr ? __half22float2(*(const __half2*)&rp[1]) : z2;
    } else { pl = pm = pr = z2; }
    {
        const uint32_t* rc = sp + rbeg * HH + col;
        cl2 = cl ? __half22float2(*(const __half2*)&rc[-1]) : z2;
        cm  = __half22float2(*(const __half2*)&rc[0]);
        cr2 = cr ? __half22float2(*(const __half2*)&rc[1]) : z2;
    }

    #pragma unroll
    for (int j = 0; j < 14; ++j) {
        const int r  = rbeg + j;
        const int nr = r + 1;
        float2 nl, nm, nr2;
        if (nr < HH) {
            const uint32_t* rn = sp + nr * HH + col;
            nl  = cl ? __half22float2(*(const __half2*)&rn[-1]) : z2;
            nm  = __half22float2(*(const __half2*)&rn[0]);
            nr2 = cr ? __half22float2(*(const __half2*)&rn[1]) : z2;
        } else { nl = nm = nr2 = z2; }
        float a0 = pl.x * wd[0] + pm.x * wd[1] + pr.x * wd[2]
                 + cl2.x * wd[3] + cm.x * wd[4] + cr2.x * wd[5]
                 + nl.x * wd[6] + nm.x * wd[7] + nr2.x * wd[8];
        float a1 = pl.y * wd[9]  + pm.y * wd[10] + pr.y * wd[11]
                 + cl2.y * wd[12] + cm.y * wd[13] + cr2.y * wd[14]
                 + nl.y * wd[15] + nm.y * wd[16] + nr2.y * wd[17];
        float v0 = clip6(s0 * a0 + b0);
        float v1 = clip6(s1 * a1 + b1);
        op[r * HH + col] = hpack2(v0, v1);
        pl = cl2; pm = cm; pr = cr2;
        cl2 = nl; cm = nm; cr2 = nr2;
    }
}

// ======================= PROJECT: resident W + cp.async X + staged epilogue ================
#define XTILE (128 * XS)          // 4608 words per X buffer
#define WCH   (64 * XS)           // 2304 words per W chunk tile
#define PSTG  136                 // fp32 stage row stride (words), 16B-aligned rows
__global__ void __launch_bounds__(256, 2) project_kernel(const float* __restrict__ x,
                                                         float* __restrict__ out)
{
    extern __shared__ uint32_t sm[];
    uint32_t* xsh = sm;                    // [2][128 px][XS] double buffer (reused as stage)
    uint32_t* wsh = sm + 2 * XTILE;        // [6][64 ch][XS] full W, pre-chunked
    float* stage  = (float*)sm;            // [64][PSTG] fp32 stage (alias of xsh, used after mainloop)

    const int n    = blockIdx.y;
    const int pix0 = blockIdx.x * 128;
    const int tid  = threadIdx.x;
    const int wid  = tid >> 5;
    const int lane = tid & 31;
    const int g    = lane >> 2;
    const int tq   = lane & 3;
    const int wm   = wid & 1;
    const int wn   = wid >> 1;

    const uint32_t xshb = (uint32_t)__cvta_generic_to_shared(xsh);
    const uint32_t wshb = (uint32_t)__cvta_generic_to_shared(wsh);
    const int lrow = (lane & 7) + ((lane >> 3) & 1) * 8;
    const int loff = (lrow * XS + ((lane >> 4) * 4)) * 4;

    // full W
    {
        const uint4* src = (const uint4*)g_wph;
        for (int i = tid; i < 3072; i += 256) {
            int c = i / 48;
            int w = (i % 48) * 4;
            int kt = w >> 5, j = w & 31;
            *(uint4*)&wsh[kt * WCH + c * XS + j] = src[i];
        }
    }

    const uint32_t* hbase = g_h2 + (size_t)n * 192 * HW;

    // prefetch X chunk 0
    #pragma unroll 1
    for (int idx = tid; idx < 128 * 32; idx += 256) {
        int j = idx >> 7, p = idx & 127;
        int pg = pix0 + p;
        bool v = pg < HW;
        const uint32_t* gp = hbase + (size_t)j * HW + (v ? pg : 0);
        cpasync4(xshb + (uint32_t)(p * XS + j) * 4, gp, v);
    }
    cpasync_commit();

    float acc[2][4][4];
    #pragma unroll
    for (int mt = 0; mt < 2; ++mt)
        #pragma unroll
        for (int nt = 0; nt < 4; ++nt)
            #pragma unroll
            for (int i = 0; i < 4; ++i) acc[mt][nt][i] = 0.f;

    #pragma unroll 1
    for (int kt = 0; kt < 6; ++kt) {
        const int buf = kt & 1;
        if (kt < 5) {
            const int nb = (kt + 1) & 1;
            const uint32_t* hb = hbase + (size_t)(kt + 1) * 32 * HW;
            #pragma unroll 1
            for (int idx = tid; idx < 128 * 32; idx += 256) {
                int j = idx >> 7, p = idx & 127;
                int pg = pix0 + p;
                bool v = pg < HW;
                const uint32_t* gp = hb + (size_t)j * HW + (v ? pg : 0);
                cpasync4(xshb + (uint32_t)(nb * XTILE + p * XS + j) * 4, gp, v);
            }
            cpasync_commit();
            asm volatile("cp.async.wait_group 1;" ::: "memory");
        } else {
            asm volatile("cp.async.wait_group 0;" ::: "memory");
        }
        __syncthreads();

        const uint32_t xb = xshb + (uint32_t)(buf * XTILE) * 4;
        const uint32_t wb = wshb + (uint32_t)(kt * WCH) * 4;
        #pragma unroll
        for (int s = 0; s < 4; ++s) {
            const int soff = s * 32;
            uint32_t ah[2][4], bh[2][4];
            #pragma unroll
            for (int mt = 0; mt < 2; ++mt) {
                uint32_t off = (uint32_t)((wm * 32 + mt * 16) * XS * 4 + soff) + loff;
                ldsm4(ah[mt], wb + off);
            }
            #pragma unroll
            for (int q = 0; q < 2; ++q) {
                uint32_t off = (uint32_t)((wn * 32 + q * 16) * XS * 4 + soff) + loff;
                ldsm4(bh[q], xb + off);
            }
            #pragma unroll
            for (int mt = 0; mt < 2; ++mt)
                #pragma unroll
                for (int q = 0; q < 2; ++q) {
                    mma16816(acc[mt][2*q],   ah[mt], bh[q][0], bh[q][2]);
                    mma16816(acc[mt][2*q+1], ah[mt], bh[q][1], bh[q][3]);
                }
        }
        __syncthreads();
    }

    // ---- epilogue: BN3 to stage (xsh region is dead now) ----
    #pragma unroll
    for (int mt = 0; mt < 2; ++mt) {
        int c0 = wm * 32 + mt * 16 + g;
        int c8 = c0 + 8;
        float s0 = g_s3[c0], h0 = g_sh3[c0];
        float s8 = g_s3[c8], h8 = g_sh3[c8];
        #pragma unroll
        for (int nt = 0; nt < 4; ++nt) {
            int pl = wn * 32 + nt * 8 + 2 * tq;
            *(float2*)&stage[c0 * PSTG + pl] = make_float2(s0 * acc[mt][nt][0] + h0,
                                                           s0 * acc[mt][nt][1] + h0);
            *(float2*)&stage[c8 * PSTG + pl] = make_float2(s8 * acc[mt][nt][2] + h8,
                                                           s8 * acc[mt][nt][3] + h8);
        }
    }
    __syncthreads();
    // ---- coalesced copy-out with residual add ----
    for (int i = tid; i < 2048; i += 256) {
        int c = i >> 5, k = i & 31;
        int pg = pix0 + 4 * k;
        if (pg < HW) {
            float4 v = *(float4*)&stage[c * PSTG + 4 * k];
            size_t off = ((size_t)(n * C1 + c)) * HW + pg;
            const float4 r = *(const float4*)(x + off);
            v.x += r.x; v.y += r.y; v.z += r.z; v.w += r.w;
            *(float4*)(out + off) = v;
        }
    }
}

// ---------------- launch ----------------
extern "C" void kernel_launch(void* const* d_in, const int* in_sizes, int n_in,
                              void* d_out, int out_size)
{
    const float* x        = (const float*)d_in[0];
    const float* w_expand = (const float*)d_in[1];
    const float* g1 = (const float*)d_in[2];
    const float* b1 = (const float*)d_in[3];
    const float* m1 = (const float*)d_in[4];
    const float* v1 = (const float*)d_in[5];
    const float* w_dw  = (const float*)d_in[6];
    const float* w_ctx = (const float*)d_in[7];
    const float* g2 = (const float*)d_in[8];
    const float* b2 = (const float*)d_in[9];
    const float* m2 = (const float*)d_in[10];
    const float* v2 = (const float*)d_in[11];
    const float* w_proj = (const float*)d_in[12];
    const float* g3 = (const float*)d_in[13];
    const float* b3 = (const float*)d_in[14];
    const float* m3 = (const float*)d_in[15];
    const float* v3 = (const float*)d_in[16];
    float* out = (float*)d_out;

    const int smem_expand  = (128 * XS + 384 * XS + 64 * ESTG) * (int)sizeof(uint32_t); // 91136
    const int smem_project = (2 * XTILE + 6 * WCH) * (int)sizeof(uint32_t);             // 92160
    cudaFuncSetAttribute((const void*)expand_kernel,
                         cudaFuncAttributeMaxDynamicSharedMemorySize, smem_expand);
    cudaFuncSetAttribute((const void*)project_kernel,
                         cudaFuncAttributeMaxDynamicSharedMemorySize, smem_project);

    prep_kernel<<<1, 512>>>(g1, b1, m1, v1, g2, b2, m2, v2, g3, b3, m3, v3,
                            w_expand, w_proj);
    expand_kernel<<<dim3(25, NB), 256, smem_expand>>>(x);
    ctxbias_kernel<<<NB, C2>>>(w_ctx);
    dw_kernel<<<dim3(192, NB), 224>>>(w_dw);
    project_kernel<<<dim3(25, NB), 256, smem_project>>>(x, out);
}

// round 13
// speedup vs baseline: 1.0352x; 1.0352x over previous
#include <cuda_runtime.h>
#include <cuda_fp16.h>
#include <cstdint>

#define NB  32
#define C1  64
#define C2  384
#define HH  56
#define HW  3136
#define EPSV 1e-5f
#define XS  36            // smem row stride in 32-bit words (conflict-free for ldmatrix)

// ---------------- scratch (device globals; no allocation allowed) ----------------
__device__ __half   g_hf  [(size_t)NB * C2 * HW];     // expand output fp16 planes (dw input)
__device__ uint32_t g_h2  [(size_t)NB * 192 * HW];    // dw output, packed fp16 ch-pair words
__device__ uint32_t g_weh [384 * 32];                  // w_expand fp16-pair words [c][j]
__device__ uint32_t g_wph [64 * 192];                  // w_proj   fp16-pair words [c][j]
__device__ float g_ctxsum[NB * C2];
__device__ float g_bias2 [NB * C2];
__device__ float g_s1[C2], g_sh1[C2];
__device__ float g_s2[C2], g_sh2[C2];
__device__ float g_s3[C1], g_sh3[C1];

// ---------------- helpers ----------------
__device__ __forceinline__ uint32_t hpack2(float f0, float f1) {
    __half2 H = __floats2half2_rn(f0, f1);
    return *reinterpret_cast<uint32_t*>(&H);
}

__device__ __forceinline__ void mma16816(float* c, const uint32_t* a, uint32_t b0, uint32_t b1) {
    asm volatile(
        "mma.sync.aligned.m16n8k16.row.col.f32.f16.f16.f32 "
        "{%0,%1,%2,%3},{%4,%5,%6,%7},{%8,%9},{%0,%1,%2,%3};"
        : "+f"(c[0]), "+f"(c[1]), "+f"(c[2]), "+f"(c[3])
        : "r"(a[0]), "r"(a[1]), "r"(a[2]), "r"(a[3]), "r"(b0), "r"(b1));
}

__device__ __forceinline__ void ldsm4(uint32_t* r, uint32_t addr) {
    asm volatile("ldmatrix.sync.aligned.m8n8.x4.shared.b16 {%0,%1,%2,%3},[%4];"
                 : "=r"(r[0]), "=r"(r[1]), "=r"(r[2]), "=r"(r[3]) : "r"(addr));
}

__device__ __forceinline__ void cpasync4(uint32_t dst, const void* src, bool valid) {
    asm volatile("cp.async.ca.shared.global [%0], [%1], 4, %2;"
                 :: "r"(dst), "l"(src), "r"(valid ? 4 : 0) : "memory");
}
__device__ __forceinline__ void cpasync_commit() {
    asm volatile("cp.async.commit_group;" ::: "memory");
}

__device__ __forceinline__ float clip6(float v) { return fminf(fmaxf(v, 0.f), 6.f); }

// ---------------- prep ----------------
__global__ void prep_kernel(const float* __restrict__ g1, const float* __restrict__ b1,
                            const float* __restrict__ m1, const float* __restrict__ v1,
                            const float* __restrict__ g2, const float* __restrict__ b2,
                            const float* __restrict__ m2, const float* __restrict__ v2,
                            const float* __restrict__ g3, const float* __restrict__ b3,
                            const float* __restrict__ m3, const float* __restrict__ v3,
                            const float* __restrict__ we, const float* __restrict__ wpj)
{
    int t = threadIdx.x;
    if (t < C2) {
        float s = g1[t] * rsqrtf(v1[t] + EPSV);
        g_s1[t] = s; g_sh1[t] = b1[t] - m1[t] * s;
        float s2 = g2[t] * rsqrtf(v2[t] + EPSV);
        g_s2[t] = s2; g_sh2[t] = b2[t] - m2[t] * s2;
    }
    if (t < C1) {
        float s = g3[t] * rsqrtf(v3[t] + EPSV);
        g_s3[t] = s; g_sh3[t] = b3[t] - m3[t] * s;
    }
    for (int i = t; i < NB * C2; i += blockDim.x) g_ctxsum[i] = 0.f;
    for (int i = t; i < 384 * 32; i += blockDim.x) {
        float2 wv = *(const float2*)(we + (size_t)i * 2);
        g_weh[i] = hpack2(wv.x, wv.y);
    }
    for (int i = t; i < 64 * 192; i += blockDim.x) {
        float2 wv = *(const float2*)(wpj + (size_t)i * 2);
        g_wph[i] = hpack2(wv.x, wv.y);
    }
}

// ======================= EXPAND: resident full-W, no intra-loop syncs =====================
__global__ void __launch_bounds__(256, 2) expand_kernel(const float* __restrict__ x)
{
    extern __shared__ uint32_t sm[];
    uint32_t* xsh = sm;                    // [128 px][XS]
    uint32_t* wsh = xsh + 128 * XS;        // [384 ch][XS] full W

    const int n    = blockIdx.y;
    const int pix0 = blockIdx.x * 128;
    const int tid  = threadIdx.x;
    const int wid  = tid >> 5;
    const int lane = tid & 31;
    const int g    = lane >> 2;
    const int tq   = lane & 3;
    const int wm   = wid & 1;
    const int wn   = wid >> 1;

    const uint32_t xshb = (uint32_t)__cvta_generic_to_shared(xsh);
    const uint32_t wshb = (uint32_t)__cvta_generic_to_shared(wsh);
    const int lrow = (lane & 7) + ((lane >> 3) & 1) * 8;
    const int loff = (lrow * XS + ((lane >> 4) * 4)) * 4;

    const float* xn = x + (size_t)n * C1 * HW;

    // X tile
    for (int idx = tid; idx < 128 * 32; idx += 256) {
        int j = idx >> 7, p = idx & 127;
        int pg = pix0 + p;
        float f0 = 0.f, f1 = 0.f;
        if (pg < HW) {
            f0 = xn[(size_t)(2 * j) * HW + pg];
            f1 = xn[(size_t)(2 * j + 1) * HW + pg];
        }
        xsh[p * XS + j] = hpack2(f0, f1);
    }
    // full W (uint4 loads; c*XS stays 16B-aligned since XS*4=144 ≡ 0 mod 16)
    {
        const uint4* src = (const uint4*)g_weh;
        for (int i = tid; i < 3072; i += 256) {
            int c = i >> 3, jq = (i & 7) * 4;
            *(uint4*)&wsh[c * XS + jq] = src[i];
        }
    }
    __syncthreads();

    for (int ct = 0; ct < 6; ++ct) {
        const int cbase = ct * 64;

        float acc[2][4][4];
        #pragma unroll
        for (int mt = 0; mt < 2; ++mt)
            #pragma unroll
            for (int nt = 0; nt < 4; ++nt)
                #pragma unroll
                for (int i = 0; i < 4; ++i) acc[mt][nt][i] = 0.f;

        #pragma unroll
        for (int s = 0; s < 4; ++s) {
            const int soff = s * 32;
            uint32_t ah[2][4], bh[2][4];
            #pragma unroll
            for (int mt = 0; mt < 2; ++mt) {
                uint32_t off = (uint32_t)((cbase + wm * 32 + mt * 16) * XS * 4 + soff) + loff;
                ldsm4(ah[mt], wshb + off);
            }
            #pragma unroll
            for (int q = 0; q < 2; ++q) {
                uint32_t off = (uint32_t)((wn * 32 + q * 16) * XS * 4 + soff) + loff;
                ldsm4(bh[q], xshb + off);
            }
            #pragma unroll
            for (int mt = 0; mt < 2; ++mt)
                #pragma unroll
                for (int q = 0; q < 2; ++q) {
                    mma16816(acc[mt][2*q],   ah[mt], bh[q][0], bh[q][2]);
                    mma16816(acc[mt][2*q+1], ah[mt], bh[q][1], bh[q][3]);
                }
        }

        #pragma unroll
        for (int mt = 0; mt < 2; ++mt) {
            int c0 = cbase + wm * 32 + mt * 16 + g;
            int c8 = c0 + 8;
            float s0 = g_s1[c0], h0 = g_sh1[c0];
            float s8 = g_s1[c8], h8 = g_sh1[c8];
            __half* hp0 = g_hf + ((size_t)(n * C2 + c0)) * HW;
            __half* hp8 = g_hf + ((size_t)(n * C2 + c8)) * HW;
            float rs0 = 0.f, rs8 = 0.f;
            #pragma unroll
            for (int nt = 0; nt < 4; ++nt) {
                int p = pix0 + wn * 32 + nt * 8 + 2 * tq;
                float v00 = clip6(s0 * acc[mt][nt][0] + h0);
                float v01 = clip6(s0 * acc[mt][nt][1] + h0);
                float v10 = clip6(s8 * acc[mt][nt][2] + h8);
                float v11 = clip6(s8 * acc[mt][nt][3] + h8);
                if (p < HW) {
                    *(__half2*)(hp0 + p) = __floats2half2_rn(v00, v01);
                    *(__half2*)(hp8 + p) = __floats2half2_rn(v10, v11);
                    rs0 += v00 + v01; rs8 += v10 + v11;
                }
            }
            rs0 += __shfl_xor_sync(0xffffffffu, rs0, 1);
            rs0 += __shfl_xor_sync(0xffffffffu, rs0, 2);
            rs8 += __shfl_xor_sync(0xffffffffu, rs8, 1);
            rs8 += __shfl_xor_sync(0xffffffffu, rs8, 2);
            if (tq == 0) {
                atomicAdd(&g_ctxsum[n * C2 + c0], rs0);
                atomicAdd(&g_ctxsum[n * C2 + c8], rs8);
            }
        }
    }
}

// ---------------- context bias ----------------
__global__ void ctxbias_kernel(const float* __restrict__ wctx)
{
    __shared__ float cs[C2];
    const int n = blockIdx.x;
    const int o = threadIdx.x;
    cs[o] = g_ctxsum[n * C2 + o] * (1.f / (float)HW);
    __syncthreads();
    const float* wr = wctx + o * C2;
    float a = 0.f;
    #pragma unroll 4
    for (int c = 0; c < C2; ++c) a += cs[c] * wr[c];
    g_bias2[n * C2 + o] = g_s2[o] * a + g_sh2[o];
}

// ---------------- depthwise 3x3: packed-half2 smem + sliding window ----------------
__global__ void __launch_bounds__(224) dw_kernel(const float* __restrict__ wdw)
{
    __shared__ uint32_t sp[HW];
    __shared__ float wd[18];
    __shared__ float bs[2], sc[2];

    const int jw = blockIdx.x;
    const int n  = blockIdx.y;
    const int t  = threadIdx.x;
    const int c0 = 2 * jw;

    const uint4* src0 = (const uint4*)(g_hf + ((size_t)(n * C2 + c0)) * HW);
    const uint4* src1 = (const uint4*)(g_hf + ((size_t)(n * C2 + c0 + 1)) * HW);
    #pragma unroll
    for (int i = t; i < HW / 8; i += 224) {
        uint4 a = src0[i];
        uint4 b = src1[i];
        const uint32_t* aw = (const uint32_t*)&a;
        const uint32_t* bw = (const uint32_t*)&b;
        #pragma unroll
        for (int k = 0; k < 4; ++k) {
            sp[8 * i + 2 * k]     = __byte_perm(aw[k], bw[k], 0x5410);
            sp[8 * i + 2 * k + 1] = __byte_perm(aw[k], bw[k], 0x7632);
        }
    }
    if (t < 18) wd[t] = wdw[c0 * 9 + t];
    if (t < 2)  { bs[t] = g_bias2[n * C2 + c0 + t]; sc[t] = g_s2[c0 + t]; }
    __syncthreads();

    const int col  = t % HH;
    const int q    = t / HH;
    const int rbeg = q * 14;
    const bool cl = (col > 0), cr = (col < HH - 1);
    uint32_t* op = g_h2 + ((size_t)(n * 192 + jw)) * HW;
    const float b0 = bs[0], b1 = bs[1], s0 = sc[0], s1 = sc[1];

    float2 pl, pm, pr, cl2, cm, cr2;
    const float2 z2 = make_float2(0.f, 0.f);

    if (rbeg > 0) {
        const uint32_t* rp = sp + (rbeg - 1) * HH + col;
        pl = cl ? __half22float2(*(const __half2*)&rp[-1]) : z2;
        pm = __half22float2(*(const __half2*)&rp[0]);
        pr = cr ? __half22float2(*(const __half2*)&rp[1]) : z2;
    } else { pl = pm = pr = z2; }
    {
        const uint32_t* rc = sp + rbeg * HH + col;
        cl2 = cl ? __half22float2(*(const __half2*)&rc[-1]) : z2;
        cm  = __half22float2(*(const __half2*)&rc[0]);
        cr2 = cr ? __half22float2(*(const __half2*)&rc[1]) : z2;
    }

    #pragma unroll
    for (int j = 0; j < 14; ++j) {
        const int r  = rbeg + j;
        const int nr = r + 1;
        float2 nl, nm, nr2;
        if (nr < HH) {
            const uint32_t* rn = sp + nr * HH + col;
            nl  = cl ? __half22float2(*(const __half2*)&rn[-1]) : z2;
            nm  = __half22float2(*(const __half2*)&rn[0]);
            nr2 = cr ? __half22float2(*(const __half2*)&rn[1]) : z2;
        } else { nl = nm = nr2 = z2; }
        float a0 = pl.x * wd[0] + pm.x * wd[1] + pr.x * wd[2]
                 + cl2.x * wd[3] + cm.x * wd[4] + cr2.x * wd[5]
                 + nl.x * wd[6] + nm.x * wd[7] + nr2.x * wd[8];
        float a1 = pl.y * wd[9]  + pm.y * wd[10] + pr.y * wd[11]
                 + cl2.y * wd[12] + cm.y * wd[13] + cr2.y * wd[14]
                 + nl.y * wd[15] + nm.y * wd[16] + nr2.y * wd[17];
        float v0 = clip6(s0 * a0 + b0);
        float v1 = clip6(s1 * a1 + b1);
        op[r * HH + col] = hpack2(v0, v1);
        pl = cl2; pm = cm; pr = cr2;
        cl2 = nl; cm = nm; cr2 = nr2;
    }
}

// ======================= PROJECT: resident W + triple-buffered cp.async X ================
#define XTILE (128 * XS)          // 4608 words per X buffer
#define WCH   (64 * XS)           // 2304 words per W chunk tile
__global__ void __launch_bounds__(256, 2) project_kernel(const float* __restrict__ x,
                                                         float* __restrict__ out)
{
    extern __shared__ uint32_t sm[];
    uint32_t* xsh = sm;                    // [3][128 px][XS] triple buffer
    uint32_t* wsh = sm + 3 * XTILE;        // [6][64 ch][XS] full W, pre-chunked

    const int n    = blockIdx.y;
    const int pix0 = blockIdx.x * 128;
    const int tid  = threadIdx.x;
    const int wid  = tid >> 5;
    const int lane = tid & 31;
    const int g    = lane >> 2;
    const int tq   = lane & 3;
    const int wm   = wid & 1;
    const int wn   = wid >> 1;

    const uint32_t xshb = (uint32_t)__cvta_generic_to_shared(xsh);
    const uint32_t wshb = (uint32_t)__cvta_generic_to_shared(wsh);
    const int lrow = (lane & 7) + ((lane >> 3) & 1) * 8;
    const int loff = (lrow * XS + ((lane >> 4) * 4)) * 4;

    // full W
    {
        const uint4* src = (const uint4*)g_wph;
        for (int i = tid; i < 3072; i += 256) {
            int c = i / 48;
            int w = (i % 48) * 4;
            int kt = w >> 5, j = w & 31;
            *(uint4*)&wsh[kt * WCH + c * XS + j] = src[i];
        }
    }

    const uint32_t* hbase = g_h2 + (size_t)n * 192 * HW;

    // prefetch X chunk 0 into buffer 0
    #pragma unroll 1
    for (int idx = tid; idx < 128 * 32; idx += 256) {
        int j = idx >> 7, p = idx & 127;
        int pg = pix0 + p;
        bool v = pg < HW;
        const uint32_t* gp = hbase + (size_t)j * HW + (v ? pg : 0);
        cpasync4(xshb + (uint32_t)(p * XS + j) * 4, gp, v);
    }
    cpasync_commit();

    float acc[2][4][4];
    #pragma unroll
    for (int mt = 0; mt < 2; ++mt)
        #pragma unroll
        for (int nt = 0; nt < 4; ++nt)
            #pragma unroll
            for (int i = 0; i < 4; ++i) acc[mt][nt][i] = 0.f;

    int buf = 0;
    #pragma unroll 1
    for (int kt = 0; kt < 6; ++kt) {
        if (kt < 5) {
            const int nb = (buf == 2) ? 0 : buf + 1;
            const uint32_t* hb = hbase + (size_t)(kt + 1) * 32 * HW;
            #pragma unroll 1
            for (int idx = tid; idx < 128 * 32; idx += 256) {
                int j = idx >> 7, p = idx & 127;
                int pg = pix0 + p;
                bool v = pg < HW;
                const uint32_t* gp = hb + (size_t)j * HW + (v ? pg : 0);
                cpasync4(xshb + (uint32_t)(nb * XTILE + p * XS + j) * 4, gp, v);
            }
            cpasync_commit();
            asm volatile("cp.async.wait_group 1;" ::: "memory");
        } else {
            asm volatile("cp.async.wait_group 0;" ::: "memory");
        }
        __syncthreads();   // single barrier per iteration (triple buffer ⇒ no tail sync)

        const uint32_t xb = xshb + (uint32_t)(buf * XTILE) * 4;
        const uint32_t wb = wshb + (uint32_t)(kt * WCH) * 4;
        #pragma unroll
        for (int s = 0; s < 4; ++s) {
            const int soff = s * 32;
            uint32_t ah[2][4], bh[2][4];
            #pragma unroll
            for (int mt = 0; mt < 2; ++mt) {
                uint32_t off = (uint32_t)((wm * 32 + mt * 16) * XS * 4 + soff) + loff;
                ldsm4(ah[mt], wb + off);
            }
            #pragma unroll
            for (int q = 0; q < 2; ++q) {
                uint32_t off = (uint32_t)((wn * 32 + q * 16) * XS * 4 + soff) + loff;
                ldsm4(bh[q], xb + off);
            }
            #pragma unroll
            for (int mt = 0; mt < 2; ++mt)
                #pragma unroll
                for (int q = 0; q < 2; ++q) {
                    mma16816(acc[mt][2*q],   ah[mt], bh[q][0], bh[q][2]);
                    mma16816(acc[mt][2*q+1], ah[mt], bh[q][1], bh[q][3]);
                }
        }
        buf = (buf == 2) ? 0 : buf + 1;
    }

    // epilogue: BN3 + residual (direct, overlapped stores)
    #pragma unroll
    for (int mt = 0; mt < 2; ++mt) {
        int c0 = wm * 32 + mt * 16 + g;
        int c8 = c0 + 8;
        float s0 = g_s3[c0], h0 = g_sh3[c0];
        float s8 = g_s3[c8], h8 = g_sh3[c8];
        const float* xp0 = x   + ((size_t)(n * C1 + c0)) * HW;
        const float* xp8 = x   + ((size_t)(n * C1 + c8)) * HW;
        float*       op0 = out + ((size_t)(n * C1 + c0)) * HW;
        float*       op8 = out + ((size_t)(n * C1 + c8)) * HW;
        #pragma unroll
        for (int nt = 0; nt < 4; ++nt) {
            int p = pix0 + wn * 32 + nt * 8 + 2 * tq;
            if (p < HW) {
                float2 r0 = *(const float2*)(xp0 + p);
                float2 r8 = *(const float2*)(xp8 + p);
                *(float2*)(op0 + p) = make_float2(s0 * acc[mt][nt][0] + h0 + r0.x,
                                                  s0 * acc[mt][nt][1] + h0 + r0.y);
                *(float2*)(op8 + p) = make_float2(s8 * acc[mt][nt][2] + h8 + r8.x,
                                                  s8 * acc[mt][nt][3] + h8 + r8.y);
            }
        }
    }
}

// ---------------- launch ----------------
extern "C" void kernel_launch(void* const* d_in, const int* in_sizes, int n_in,
                              void* d_out, int out_size)
{
    const float* x        = (const float*)d_in[0];
    const float* w_expand = (const float*)d_in[1];
    const float* g1 = (const float*)d_in[2];
    const float* b1 = (const float*)d_in[3];
    const float* m1 = (const float*)d_in[4];
    const float* v1 = (const float*)d_in[5];
    const float* w_dw  = (const float*)d_in[6];
    const float* w_ctx = (const float*)d_in[7];
    const float* g2 = (const float*)d_in[8];
    const float* b2 = (const float*)d_in[9];
    const float* m2 = (const float*)d_in[10];
    const float* v2 = (const float*)d_in[11];
    const float* w_proj = (const float*)d_in[12];
    const float* g3 = (const float*)d_in[13];
    const float* b3 = (const float*)d_in[14];
    const float* m3 = (const float*)d_in[15];
    const float* v3 = (const float*)d_in[16];
    float* out = (float*)d_out;

    const int smem_expand  = (128 * XS + 384 * XS) * (int)sizeof(uint32_t);      // 73728
    const int smem_project = (3 * XTILE + 6 * WCH) * (int)sizeof(uint32_t);      // 110592
    cudaFuncSetAttribute((const void*)expand_kernel,
                         cudaFuncAttributeMaxDynamicSharedMemorySize, smem_expand);
    cudaFuncSetAttribute((const void*)project_kernel,
                         cudaFuncAttributeMaxDynamicSharedMemorySize, smem_project);

    prep_kernel<<<1, 512>>>(g1, b1, m1, v1, g2, b2, m2, v2, g3, b3, m3, v3,
                            w_expand, w_proj);
    expand_kernel<<<dim3(25, NB), 256, smem_expand>>>(x);
    ctxbias_kernel<<<NB, C2>>>(w_ctx);
    dw_kernel<<<dim3(192, NB), 224>>>(w_dw);
    project_kernel<<<dim3(25, NB), 256, smem_project>>>(x, out);
}